// round 13
// baseline (speedup 1.0000x reference)
#include <cuda_runtime.h>
#include <cuda_bf16.h>

// Problem constants
#define Bn   8
#define Tn   4
#define HIDn 4096
#define Hn   32
#define Dn   128
#define SCn  4096          // cache length
#define SFn  4100          // cache + T
#define BT   32            // B*T
#define KSPLIT 8
#define KCHUNK (HIDn / KSPLIT)   // 512
#define NSPLIT 16          // cache splits (256 rows each)
#define PART_N 68          // 16 splits * 4 warps + 4 new-token rows

#define OUT_K_OFF   ((size_t)131072)                       // out elems
#define KFULL_ELEMS ((size_t)Bn * Hn * SFn * Dn)           // 134,348,800

// ---------------- scratch (no allocations allowed) ----------------
__device__ float g_qkv_part[3 * KSPLIT * BT * HIDn];   // split-K partials for q,k,v proj
__device__ float g_q[Bn * Hn * Tn * Dn];               // RoPE'd q, [b,h,t,d]
__device__ float g_pm[Bn * Hn * PART_N * Tn];          // per-partial running max (log2 domain)
__device__ float g_pl[Bn * Hn * PART_N * Tn];          // per-partial running denom
__device__ float g_pacc[Bn * Hn * PART_N * Tn * Dn];   // per-partial weighted V acc
__device__ float g_o[BT * HIDn];                       // attention out, [b*T+t, h*D+d]
__device__ float g_opart[KSPLIT * BT * HIDn];          // split-K partials for Wo gemm

// ---------------- f32x2 packed-FMA helpers (Blackwell FFMA2) ----------------
#define FMA2(d, a, b, c) \
    asm("fma.rn.f32x2 %0, %1, %2, %3;" : "=l"(d) : "l"(a), "l"(b), "l"(c))
#define PACK2BC(d, x) \
    asm("mov.b64 %0, {%1, %1};" : "=l"(d) : "r"(__float_as_uint(x)))
#define UNPACK2(lo, hi, p) \
    asm("mov.b64 {%0, %1}, %2;" : "=f"(lo), "=f"(hi) : "l"(p))

// ---------------- GEMM: Y[m,n] = sum_k X[m,k] * W[n,k] ----------------
// M=32, K=4096, N=4096. Block 256 threads computes [32m x 128n] over a
// KCHUNK k-range. Smem-tiled, coalesced global loads, XOR-swizzled W tile
// (conflict-free transpose STS + compute LDS.128), f32x2 packed FMA inner loop.
__global__ void __launch_bounds__(256) gemm32(
        const float* __restrict__ X,   // nullptr -> use g_o
        const float* __restrict__ W0,
        const float* __restrict__ W1,
        const float* __restrict__ W2) {
    __shared__ float Xs[32][34];    // [k][m], stride 34 (2-way STS conflict, fine)
    __shared__ float Ws[32][132];   // [k][swizzled n], stride 132 -> conflict-free

    const float* Xp = X ? X : g_o;
    float* part = X ? g_qkv_part : g_opart;
    int mat = blockIdx.z;
    const float* W = (mat == 0) ? W0 : (mat == 1 ? W1 : W2);

    int tid = threadIdx.x;
    int lk = tid & 7;        // float4 index along k for loads (0..7)
    int lm = tid >> 3;       // row index for loads (0..31)
    int ng = tid & 31;       // n-group in compute (0..31) -> cols ng*4..+3
    int mg = tid >> 5;       // m-group / warp id (0..7)  -> rows mg*4..+3

    int n0blk = blockIdx.x * 128;
    int k0 = blockIdx.y * KCHUNK;

    unsigned long long acc[2][4];   // [m-pair][n], each is f32x2 (m0,m1)
#pragma unroll
    for (int i = 0; i < 2; i++)
#pragma unroll
        for (int j = 0; j < 4; j++) acc[i][j] = 0ull;

    const float* xg = Xp + (size_t)lm * HIDn + k0 + lk * 4;
    const float* wg = W + (size_t)(n0blk + lm) * HIDn + k0 + lk * 4;

    for (int kt = 0; kt < KCHUNK; kt += 32) {
        // --- load X tile [32m x 32k], store transposed ---
        float4 xv = *(const float4*)(xg + kt);
        Xs[lk * 4 + 0][lm] = xv.x;
        Xs[lk * 4 + 1][lm] = xv.y;
        Xs[lk * 4 + 2][lm] = xv.z;
        Xs[lk * 4 + 3][lm] = xv.w;
        // --- load W tile [128n x 32k], store transposed + XOR swizzle ---
#pragma unroll
        for (int it = 0; it < 4; it++) {
            int n = lm + it * 32;
            float4 wv = *(const float4*)(wg + (size_t)(it * 32) * HIDn + kt);
            int c = (((n >> 2) ^ lk) << 2) + (n & 3);
            Ws[lk * 4 + 0][c] = wv.x;
            Ws[lk * 4 + 1][c] = wv.y;
            Ws[lk * 4 + 2][c] = wv.z;
            Ws[lk * 4 + 3][c] = wv.w;
        }
        __syncthreads();

#pragma unroll
        for (int kk = 0; kk < 32; kk++) {
            int k4 = kk >> 2;
            // x pairs (broadcast across warp: all lanes share mg)
            unsigned long long xp0 = *(const unsigned long long*)&Xs[kk][mg * 4];
            unsigned long long xp1 = *(const unsigned long long*)&Xs[kk][mg * 4 + 2];
            // w: de-swizzled LDS.128 (ng^k4 is a lane permutation -> conflict-free)
            float4 wv = *(const float4*)&Ws[kk][((ng ^ k4) << 2)];
            unsigned long long wb0, wb1, wb2, wb3;
            PACK2BC(wb0, wv.x); PACK2BC(wb1, wv.y);
            PACK2BC(wb2, wv.z); PACK2BC(wb3, wv.w);
            FMA2(acc[0][0], xp0, wb0, acc[0][0]);
            FMA2(acc[0][1], xp0, wb1, acc[0][1]);
            FMA2(acc[0][2], xp0, wb2, acc[0][2]);
            FMA2(acc[0][3], xp0, wb3, acc[0][3]);
            FMA2(acc[1][0], xp1, wb0, acc[1][0]);
            FMA2(acc[1][1], xp1, wb1, acc[1][1]);
            FMA2(acc[1][2], xp1, wb2, acc[1][2]);
            FMA2(acc[1][3], xp1, wb3, acc[1][3]);
        }
        __syncthreads();
    }

    // epilogue: thread owns rows mg*4..mg*4+3, cols n0blk + ng*4..+3
    float* pp = part + ((size_t)(mat * KSPLIT + blockIdx.y) * BT) * HIDn + n0blk + ng * 4;
#pragma unroll
    for (int mp = 0; mp < 2; mp++) {
        float lo[4], hi[4];
#pragma unroll
        for (int j = 0; j < 4; j++) UNPACK2(lo[j], hi[j], acc[mp][j]);
        *(float4*)(pp + (size_t)(mg * 4 + 2 * mp) * HIDn) =
            make_float4(lo[0], lo[1], lo[2], lo[3]);
        *(float4*)(pp + (size_t)(mg * 4 + 2 * mp + 1) * HIDn) =
            make_float4(hi[0], hi[1], hi[2], hi[3]);
    }
}

// ---------------- RoPE + scatter new k/v into d_out, q into scratch ----------------
__global__ void rope_scatter(const float* __restrict__ cs, const float* __restrict__ sn,
                             float* __restrict__ out) {
    int idx = blockIdx.x * blockDim.x + threadIdx.x;  // < 131072
    int d = idx & 127;
    int h = (idx >> 7) & 31;
    int t = (idx >> 12) & 3;
    int b = idx >> 14;
    int row = b * Tn + t;
    int col = h * Dn + d;
    int col2 = h * Dn + ((d + 64) & 127);

    float q = 0.f, k = 0.f, v = 0.f, q2 = 0.f, k2 = 0.f;
#pragma unroll
    for (int kz = 0; kz < KSPLIT; kz++) {
        size_t r = (size_t)row * HIDn;
        q  += g_qkv_part[(size_t)(kz)              * BT * HIDn + r + col];
        q2 += g_qkv_part[(size_t)(kz)              * BT * HIDn + r + col2];
        k  += g_qkv_part[(size_t)(KSPLIT + kz)     * BT * HIDn + r + col];
        k2 += g_qkv_part[(size_t)(KSPLIT + kz)     * BT * HIDn + r + col2];
        v  += g_qkv_part[(size_t)(2 * KSPLIT + kz) * BT * HIDn + r + col];
    }
    float sgn = (d < 64) ? -1.f : 1.f;   // rotate_half: [-x[64:], x[:64]]
    float c = cs[row * Dn + d];
    float s = sn[row * Dn + d];
    float qr = q * c + sgn * q2 * s;
    float kr = k * c + sgn * k2 * s;

    g_q[((size_t)(b * Hn + h) * Tn + t) * Dn + d] = qr;
    size_t ko = OUT_K_OFF + ((size_t)(b * Hn + h) * SFn + SCn + t) * Dn + d;
    out[ko] = kr;                 // k_full new row
    out[ko + KFULL_ELEMS] = v;    // v_full new row (no RoPE on v)
}

// online-softmax update for one k/v row (scores in log2 domain)
__device__ __forceinline__ void online_row(const float4 kc, const float4 vc,
                                           const float4 qf[4],
                                           float m[4], float l[4], float4 acc[4]) {
    const float sc = 0.088388347648318447f * 1.4426950408889634f;  // 1/sqrt(128) * log2(e)
    float p[4];
#pragma unroll
    for (int t = 0; t < 4; t++)
        p[t] = qf[t].x * kc.x + qf[t].y * kc.y + qf[t].z * kc.z + qf[t].w * kc.w;
#pragma unroll
    for (int off = 16; off; off >>= 1) {
#pragma unroll
        for (int t = 0; t < 4; t++)
            p[t] += __shfl_xor_sync(0xffffffffu, p[t], off);
    }
#pragma unroll
    for (int t = 0; t < 4; t++) {
        float s = p[t] * sc;
        if (s > m[t]) {                       // lazy rescale: rare after warmup
            float f = exp2f(m[t] - s);
            m[t] = s;
            l[t] *= f;
            acc[t].x *= f; acc[t].y *= f; acc[t].z *= f; acc[t].w *= f;
        }
        float e = exp2f(s - m[t]);
        l[t] += e;
        acc[t].x += e * vc.x; acc[t].y += e * vc.y;
        acc[t].z += e * vc.z; acc[t].w += e * vc.w;
    }
}

// ---------------- fused cache copy + flash-decode partial attention ----------------
// grid (17, H, B), block 128 (4 warps). splits 0..15: 256 cache rows each
// (copied to k_full/v_full while accumulating). split 16: the 4 new rows.
__global__ void attn_copy(const float* __restrict__ ck, const float* __restrict__ cv,
                          float* out) {
    int split = blockIdx.x;
    int h = blockIdx.y, b = blockIdx.z;
    int bh = b * Hn + h;
    int wid = threadIdx.x >> 5, lane = threadIdx.x & 31;

    float4 qf[4];
#pragma unroll
    for (int t = 0; t < 4; t++)
        qf[t] = *(const float4*)&g_q[((size_t)bh * Tn + t) * Dn + lane * 4];

    float m[4], l[4];
    float4 acc[4];
#pragma unroll
    for (int t = 0; t < 4; t++) { m[t] = -1e30f; l[t] = 0.f; acc[t] = make_float4(0, 0, 0, 0); }

    if (split < NSPLIT) {
        int s0 = split * 256 + wid * 64;
        const float* kp = ck + ((size_t)bh * SCn + s0) * Dn + lane * 4;
        const float* vp = cv + ((size_t)bh * SCn + s0) * Dn + lane * 4;
        float* kop = out + OUT_K_OFF + ((size_t)bh * SFn + s0) * Dn + lane * 4;
        float* vop = kop + KFULL_ELEMS;

        float4 kc = *(const float4*)kp;
        float4 vc = *(const float4*)vp;
        for (int r = 0; r < 64; r++) {
            float4 kn = kc, vn = vc;
            if (r < 63) {   // prefetch next row while processing current
                kn = *(const float4*)(kp + (size_t)(r + 1) * Dn);
                vn = *(const float4*)(vp + (size_t)(r + 1) * Dn);
            }
            *(float4*)(kop + (size_t)r * Dn) = kc;   // fused cache->k_full copy
            *(float4*)(vop + (size_t)r * Dn) = vc;
            online_row(kc, vc, qf, m, l, acc);
            kc = kn; vc = vn;
        }
    } else {
        // new rows already written to d_out by rope_scatter; read back, no copy
        const float* kr = out + OUT_K_OFF + ((size_t)bh * SFn + SCn + wid) * Dn + lane * 4;
        float4 kc = *(const float4*)kr;
        float4 vc = *(const float4*)(kr + KFULL_ELEMS);
        online_row(kc, vc, qf, m, l, acc);
    }

    int slot = (split < NSPLIT) ? split * 4 + wid : 64 + wid;
    size_t base = ((size_t)bh * PART_N + slot) * Tn;
    if (lane == 0) {
#pragma unroll
        for (int t = 0; t < 4; t++) { g_pm[base + t] = m[t]; g_pl[base + t] = l[t]; }
    }
#pragma unroll
    for (int t = 0; t < 4; t++)
        *(float4*)&g_pacc[(base + t) * Dn + lane * 4] = acc[t];
}

// ---------------- combine split partials -> attention output ----------------
__global__ void combine_splits() {
    int bh = blockIdx.x;
    int b = bh >> 5, h = bh & 31;
    __shared__ float sh_e[PART_N][4];
    __shared__ float sh_den[4];
    int tid = threadIdx.x;
    size_t base = (size_t)bh * PART_N * Tn;

    if (tid < 4) {
        int t = tid;
        float mx = -1e30f;
        for (int p = 0; p < PART_N; p++)
            mx = fmaxf(mx, g_pm[base + (size_t)p * Tn + t]);
        float den = 0.f;
        for (int p = 0; p < PART_N; p++) {
            float e = exp2f(g_pm[base + (size_t)p * Tn + t] - mx);
            sh_e[p][t] = e;
            den += g_pl[base + (size_t)p * Tn + t] * e;
        }
        sh_den[t] = den;
    }
    __syncthreads();

    int d = tid;  // 128 threads
#pragma unroll
    for (int t = 0; t < 4; t++) {
        float num = 0.f;
        for (int p = 0; p < PART_N; p++)
            num += sh_e[p][t] * g_pacc[(base + (size_t)p * Tn + t) * Dn + d];
        g_o[(size_t)(b * Tn + t) * HIDn + h * Dn + d] = num / sh_den[t];
    }
}

// ---------------- sum Wo split-K partials into final out ----------------
__global__ void finalize(float* __restrict__ out) {
    int idx = blockIdx.x * blockDim.x + threadIdx.x;  // < 131072
    float s = 0.f;
#pragma unroll
    for (int kz = 0; kz < KSPLIT; kz++)
        s += g_opart[(size_t)kz * BT * HIDn + idx];
    out[idx] = s;
}

extern "C" void kernel_launch(void* const* d_in, const int* in_sizes, int n_in,
                              void* d_out, int out_size) {
    const float* hidden  = (const float*)d_in[0];
    const float* cache_k = (const float*)d_in[1];
    const float* cache_v = (const float*)d_in[2];
    const float* cosp    = (const float*)d_in[3];
    const float* sinp    = (const float*)d_in[4];
    const float* Wq      = (const float*)d_in[5];
    const float* Wk      = (const float*)d_in[6];
    const float* Wv      = (const float*)d_in[7];
    const float* Wo      = (const float*)d_in[8];
    float* out = (float*)d_out;

    // 1) QKV projections (split-K partials)
    gemm32<<<dim3(32, KSPLIT, 3), 256>>>(hidden, Wq, Wk, Wv);
    // 2) reduce split-K + RoPE + scatter new k/v rows into d_out, q into scratch
    rope_scatter<<<512, 256>>>(cosp, sinp, out);
    // 3) fused cache copy + flash-decode partials
    attn_copy<<<dim3(NSPLIT + 1, Hn, Bn), 128>>>(cache_k, cache_v, out);
    // 4) combine partials
    combine_splits<<<Bn * Hn, 128>>>();
    // 5) output projection (split-K partials, X = g_o selected by nullptr)
    gemm32<<<dim3(32, KSPLIT, 1), 256>>>(nullptr, Wo, Wo, Wo);
    // 6) reduce into d_out
    finalize<<<512, 256>>>(out);
}

// round 14
// speedup vs baseline: 1.0007x; 1.0007x over previous
#include <cuda_runtime.h>
#include <cuda_bf16.h>

// Problem constants
#define Bn   8
#define Tn   4
#define HIDn 4096
#define Hn   32
#define Dn   128
#define SCn  4096          // cache length
#define SFn  4100          // cache + T
#define BT   32            // B*T
#define KSPLIT 8
#define KCHUNK (HIDn / KSPLIT)   // 512
#define NSPLIT 16          // cache splits (256 rows each)
#define PART_N 68          // 16 splits * 4 warps + 4 new-token rows

#define OUT_K_OFF   ((size_t)131072)                       // out elems
#define KFULL_ELEMS ((size_t)Bn * Hn * SFn * Dn)           // 134,348,800

// ---------------- scratch (no allocations allowed) ----------------
__device__ float g_qkv_part[3 * KSPLIT * BT * HIDn];   // split-K partials for q,k,v proj
__device__ float g_q[Bn * Hn * Tn * Dn];               // RoPE'd q, [b,h,t,d]
__device__ float g_pm[Bn * Hn * PART_N * Tn];          // per-partial running max (log2 domain)
__device__ float g_pl[Bn * Hn * PART_N * Tn];          // per-partial running denom
__device__ float g_pacc[Bn * Hn * PART_N * Tn * Dn];   // per-partial weighted V acc
__device__ float g_o[BT * HIDn];                       // attention out, [b*T+t, h*D+d]
__device__ float g_opart[KSPLIT * BT * HIDn];          // split-K partials for Wo gemm

// ---------------- f32x2 packed-FMA helpers (Blackwell FFMA2) ----------------
#define FMA2(d, a, b, c) \
    asm("fma.rn.f32x2 %0, %1, %2, %3;" : "=l"(d) : "l"(a), "l"(b), "l"(c))
#define PACK2BC(d, x) \
    asm("mov.b64 %0, {%1, %1};" : "=l"(d) : "r"(__float_as_uint(x)))
#define UNPACK2(lo, hi, p) \
    asm("mov.b64 {%0, %1}, %2;" : "=f"(lo), "=f"(hi) : "l"(p))

// ---------------- GEMM: Y[m,n] = sum_k X[m,k] * W[n,k] ----------------
// M=32, K=4096, N=4096. Block 256 threads computes [32m x 128n] over a
// KCHUNK k-range. Smem-tiled, coalesced global loads, XOR-swizzled W tile
// (conflict-free transpose STS + compute LDS.128), f32x2 packed FMA inner loop.
__global__ void __launch_bounds__(256) gemm32(
        const float* __restrict__ X,   // nullptr -> use g_o
        const float* __restrict__ W0,
        const float* __restrict__ W1,
        const float* __restrict__ W2) {
    __shared__ float Xs[32][34];    // [k][m], stride 34 (2-way STS conflict, fine)
    __shared__ float Ws[32][132];   // [k][swizzled n], stride 132 -> conflict-free

    const float* Xp = X ? X : g_o;
    float* part = X ? g_qkv_part : g_opart;
    int mat = blockIdx.z;
    const float* W = (mat == 0) ? W0 : (mat == 1 ? W1 : W2);

    int tid = threadIdx.x;
    int lk = tid & 7;        // float4 index along k for loads (0..7)
    int lm = tid >> 3;       // row index for loads (0..31)
    int ng = tid & 31;       // n-group in compute (0..31) -> cols ng*4..+3
    int mg = tid >> 5;       // m-group / warp id (0..7)  -> rows mg*4..+3

    int n0blk = blockIdx.x * 128;
    int k0 = blockIdx.y * KCHUNK;

    unsigned long long acc[2][4];   // [m-pair][n], each is f32x2 (m0,m1)
#pragma unroll
    for (int i = 0; i < 2; i++)
#pragma unroll
        for (int j = 0; j < 4; j++) acc[i][j] = 0ull;

    const float* xg = Xp + (size_t)lm * HIDn + k0 + lk * 4;
    const float* wg = W + (size_t)(n0blk + lm) * HIDn + k0 + lk * 4;

    for (int kt = 0; kt < KCHUNK; kt += 32) {
        // --- load X tile [32m x 32k], store transposed ---
        float4 xv = *(const float4*)(xg + kt);
        Xs[lk * 4 + 0][lm] = xv.x;
        Xs[lk * 4 + 1][lm] = xv.y;
        Xs[lk * 4 + 2][lm] = xv.z;
        Xs[lk * 4 + 3][lm] = xv.w;
        // --- load W tile [128n x 32k], store transposed + XOR swizzle ---
#pragma unroll
        for (int it = 0; it < 4; it++) {
            int n = lm + it * 32;
            float4 wv = *(const float4*)(wg + (size_t)(it * 32) * HIDn + kt);
            int c = (((n >> 2) ^ lk) << 2) + (n & 3);
            Ws[lk * 4 + 0][c] = wv.x;
            Ws[lk * 4 + 1][c] = wv.y;
            Ws[lk * 4 + 2][c] = wv.z;
            Ws[lk * 4 + 3][c] = wv.w;
        }
        __syncthreads();

#pragma unroll
        for (int kk = 0; kk < 32; kk++) {
            int k4 = kk >> 2;
            // x pairs (broadcast across warp: all lanes share mg)
            unsigned long long xp0 = *(const unsigned long long*)&Xs[kk][mg * 4];
            unsigned long long xp1 = *(const unsigned long long*)&Xs[kk][mg * 4 + 2];
            // w: de-swizzled LDS.128 (ng^k4 is a lane permutation -> conflict-free)
            float4 wv = *(const float4*)&Ws[kk][((ng ^ k4) << 2)];
            unsigned long long wb0, wb1, wb2, wb3;
            PACK2BC(wb0, wv.x); PACK2BC(wb1, wv.y);
            PACK2BC(wb2, wv.z); PACK2BC(wb3, wv.w);
            FMA2(acc[0][0], xp0, wb0, acc[0][0]);
            FMA2(acc[0][1], xp0, wb1, acc[0][1]);
            FMA2(acc[0][2], xp0, wb2, acc[0][2]);
            FMA2(acc[0][3], xp0, wb3, acc[0][3]);
            FMA2(acc[1][0], xp1, wb0, acc[1][0]);
            FMA2(acc[1][1], xp1, wb1, acc[1][1]);
            FMA2(acc[1][2], xp1, wb2, acc[1][2]);
            FMA2(acc[1][3], xp1, wb3, acc[1][3]);
        }
        __syncthreads();
    }

    // epilogue: thread owns rows mg*4..mg*4+3, cols n0blk + ng*4..+3
    float* pp = part + ((size_t)(mat * KSPLIT + blockIdx.y) * BT) * HIDn + n0blk + ng * 4;
#pragma unroll
    for (int mp = 0; mp < 2; mp++) {
        float lo[4], hi[4];
#pragma unroll
        for (int j = 0; j < 4; j++) UNPACK2(lo[j], hi[j], acc[mp][j]);
        *(float4*)(pp + (size_t)(mg * 4 + 2 * mp) * HIDn) =
            make_float4(lo[0], lo[1], lo[2], lo[3]);
        *(float4*)(pp + (size_t)(mg * 4 + 2 * mp + 1) * HIDn) =
            make_float4(hi[0], hi[1], hi[2], hi[3]);
    }
}

// ---------------- RoPE + scatter new k/v into d_out, q into scratch ----------------
__global__ void rope_scatter(const float* __restrict__ cs, const float* __restrict__ sn,
                             float* __restrict__ out) {
    int idx = blockIdx.x * blockDim.x + threadIdx.x;  // < 131072
    int d = idx & 127;
    int h = (idx >> 7) & 31;
    int t = (idx >> 12) & 3;
    int b = idx >> 14;
    int row = b * Tn + t;
    int col = h * Dn + d;
    int col2 = h * Dn + ((d + 64) & 127);

    float q = 0.f, k = 0.f, v = 0.f, q2 = 0.f, k2 = 0.f;
#pragma unroll
    for (int kz = 0; kz < KSPLIT; kz++) {
        size_t r = (size_t)row * HIDn;
        q  += g_qkv_part[(size_t)(kz)              * BT * HIDn + r + col];
        q2 += g_qkv_part[(size_t)(kz)              * BT * HIDn + r + col2];
        k  += g_qkv_part[(size_t)(KSPLIT + kz)     * BT * HIDn + r + col];
        k2 += g_qkv_part[(size_t)(KSPLIT + kz)     * BT * HIDn + r + col2];
        v  += g_qkv_part[(size_t)(2 * KSPLIT + kz) * BT * HIDn + r + col];
    }
    float sgn = (d < 64) ? -1.f : 1.f;   // rotate_half: [-x[64:], x[:64]]
    float c = cs[row * Dn + d];
    float s = sn[row * Dn + d];
    float qr = q * c + sgn * q2 * s;
    float kr = k * c + sgn * k2 * s;

    g_q[((size_t)(b * Hn + h) * Tn + t) * Dn + d] = qr;
    size_t ko = OUT_K_OFF + ((size_t)(b * Hn + h) * SFn + SCn + t) * Dn + d;
    out[ko] = kr;                 // k_full new row
    out[ko + KFULL_ELEMS] = v;    // v_full new row (no RoPE on v)
}

// online-softmax update for one k/v row (scores in log2 domain)
__device__ __forceinline__ void online_row(const float4 kc, const float4 vc,
                                           const float4 qf[4],
                                           float m[4], float l[4], float4 acc[4]) {
    const float sc = 0.088388347648318447f * 1.4426950408889634f;  // 1/sqrt(128) * log2(e)
    float p[4];
#pragma unroll
    for (int t = 0; t < 4; t++)
        p[t] = qf[t].x * kc.x + qf[t].y * kc.y + qf[t].z * kc.z + qf[t].w * kc.w;
#pragma unroll
    for (int off = 16; off; off >>= 1) {
#pragma unroll
        for (int t = 0; t < 4; t++)
            p[t] += __shfl_xor_sync(0xffffffffu, p[t], off);
    }
#pragma unroll
    for (int t = 0; t < 4; t++) {
        float s = p[t] * sc;
        if (s > m[t]) {                       // lazy rescale: rare after warmup
            float f = exp2f(m[t] - s);
            m[t] = s;
            l[t] *= f;
            acc[t].x *= f; acc[t].y *= f; acc[t].z *= f; acc[t].w *= f;
        }
        float e = exp2f(s - m[t]);
        l[t] += e;
        acc[t].x += e * vc.x; acc[t].y += e * vc.y;
        acc[t].z += e * vc.z; acc[t].w += e * vc.w;
    }
}

// ---------------- fused cache copy + flash-decode partial attention ----------------
// grid (17, H, B), block 128 (4 warps). splits 0..15: 256 cache rows each
// (copied to k_full/v_full while accumulating). split 16: the 4 new rows.
__global__ void attn_copy(const float* __restrict__ ck, const float* __restrict__ cv,
                          float* out) {
    int split = blockIdx.x;
    int h = blockIdx.y, b = blockIdx.z;
    int bh = b * Hn + h;
    int wid = threadIdx.x >> 5, lane = threadIdx.x & 31;

    float4 qf[4];
#pragma unroll
    for (int t = 0; t < 4; t++)
        qf[t] = *(const float4*)&g_q[((size_t)bh * Tn + t) * Dn + lane * 4];

    float m[4], l[4];
    float4 acc[4];
#pragma unroll
    for (int t = 0; t < 4; t++) { m[t] = -1e30f; l[t] = 0.f; acc[t] = make_float4(0, 0, 0, 0); }

    if (split < NSPLIT) {
        int s0 = split * 256 + wid * 64;
        const float* kp = ck + ((size_t)bh * SCn + s0) * Dn + lane * 4;
        const float* vp = cv + ((size_t)bh * SCn + s0) * Dn + lane * 4;
        float* kop = out + OUT_K_OFF + ((size_t)bh * SFn + s0) * Dn + lane * 4;
        float* vop = kop + KFULL_ELEMS;

        float4 kc = *(const float4*)kp;
        float4 vc = *(const float4*)vp;
        for (int r = 0; r < 64; r++) {
            float4 kn = kc, vn = vc;
            if (r < 63) {   // prefetch next row while processing current
                kn = *(const float4*)(kp + (size_t)(r + 1) * Dn);
                vn = *(const float4*)(vp + (size_t)(r + 1) * Dn);
            }
            *(float4*)(kop + (size_t)r * Dn) = kc;   // fused cache->k_full copy
            *(float4*)(vop + (size_t)r * Dn) = vc;
            online_row(kc, vc, qf, m, l, acc);
            kc = kn; vc = vn;
        }
    } else {
        // new rows already written to d_out by rope_scatter; read back, no copy
        const float* kr = out + OUT_K_OFF + ((size_t)bh * SFn + SCn + wid) * Dn + lane * 4;
        float4 kc = *(const float4*)kr;
        float4 vc = *(const float4*)(kr + KFULL_ELEMS);
        online_row(kc, vc, qf, m, l, acc);
    }

    int slot = (split < NSPLIT) ? split * 4 + wid : 64 + wid;
    size_t base = ((size_t)bh * PART_N + slot) * Tn;
    if (lane == 0) {
#pragma unroll
        for (int t = 0; t < 4; t++) { g_pm[base + t] = m[t]; g_pl[base + t] = l[t]; }
    }
#pragma unroll
    for (int t = 0; t < 4; t++)
        *(float4*)&g_pacc[(base + t) * Dn + lane * 4] = acc[t];
}

// ---------------- combine split partials -> attention output ----------------
__global__ void combine_splits() {
    int bh = blockIdx.x;
    int b = bh >> 5, h = bh & 31;
    __shared__ float sh_e[PART_N][4];
    __shared__ float sh_den[4];
    int tid = threadIdx.x;
    size_t base = (size_t)bh * PART_N * Tn;

    if (tid < 4) {
        int t = tid;
        float mx = -1e30f;
        for (int p = 0; p < PART_N; p++)
            mx = fmaxf(mx, g_pm[base + (size_t)p * Tn + t]);
        float den = 0.f;
        for (int p = 0; p < PART_N; p++) {
            float e = exp2f(g_pm[base + (size_t)p * Tn + t] - mx);
            sh_e[p][t] = e;
            den += g_pl[base + (size_t)p * Tn + t] * e;
        }
        sh_den[t] = den;
    }
    __syncthreads();

    int d = tid;  // 128 threads
#pragma unroll
    for (int t = 0; t < 4; t++) {
        float num = 0.f;
        for (int p = 0; p < PART_N; p++)
            num += sh_e[p][t] * g_pacc[(base + (size_t)p * Tn + t) * Dn + d];
        g_o[(size_t)(b * Tn + t) * HIDn + h * Dn + d] = num / sh_den[t];
    }
}

// ---------------- sum Wo split-K partials into final out ----------------
__global__ void finalize(float* __restrict__ out) {
    int idx = blockIdx.x * blockDim.x + threadIdx.x;  // < 131072
    float s = 0.f;
#pragma unroll
    for (int kz = 0; kz < KSPLIT; kz++)
        s += g_opart[(size_t)kz * BT * HIDn + idx];
    out[idx] = s;
}

extern "C" void kernel_launch(void* const* d_in, const int* in_sizes, int n_in,
                              void* d_out, int out_size) {
    const float* hidden  = (const float*)d_in[0];
    const float* cache_k = (const float*)d_in[1];
    const float* cache_v = (const float*)d_in[2];
    const float* cosp    = (const float*)d_in[3];
    const float* sinp    = (const float*)d_in[4];
    const float* Wq      = (const float*)d_in[5];
    const float* Wk      = (const float*)d_in[6];
    const float* Wv      = (const float*)d_in[7];
    const float* Wo      = (const float*)d_in[8];
    float* out = (float*)d_out;

    // 1) QKV projections (split-K partials)
    gemm32<<<dim3(32, KSPLIT, 3), 256>>>(hidden, Wq, Wk, Wv);
    // 2) reduce split-K + RoPE + scatter new k/v rows into d_out, q into scratch
    rope_scatter<<<512, 256>>>(cosp, sinp, out);
    // 3) fused cache copy + flash-decode partials
    attn_copy<<<dim3(NSPLIT + 1, Hn, Bn), 128>>>(cache_k, cache_v, out);
    // 4) combine partials
    combine_splits<<<Bn * Hn, 128>>>();
    // 5) output projection (split-K partials, X = g_o selected by nullptr)
    gemm32<<<dim3(32, KSPLIT, 1), 256>>>(nullptr, Wo, Wo, Wo);
    // 6) reduce into d_out
    finalize<<<512, 256>>>(out);
}

// round 15
// speedup vs baseline: 1.0493x; 1.0485x over previous
#include <cuda_runtime.h>
#include <cuda_bf16.h>

// Problem constants
#define Bn   8
#define Tn   4
#define HIDn 4096
#define Hn   32
#define Dn   128
#define SCn  4096          // cache length
#define SFn  4100          // cache + T
#define BT   32            // B*T
#define KSPLIT 8
#define KCHUNK (HIDn / KSPLIT)   // 512
#define NSPLIT 16          // cache splits (256 rows each)
#define PART_N 17          // 16 cache splits + 1 new-token slot (warps merged in-block)

#define OUT_K_OFF   ((size_t)131072)                       // out elems
#define KFULL_ELEMS ((size_t)Bn * Hn * SFn * Dn)           // 134,348,800

// ---------------- scratch (no allocations allowed) ----------------
__device__ float g_qkv_part[3 * KSPLIT * BT * HIDn];   // split-K partials for q,k,v proj
__device__ float g_q[Bn * Hn * Tn * Dn];               // RoPE'd q, [b,h,t,d]
__device__ float g_pm[Bn * Hn * PART_N * Tn];          // per-partial running max (log2 domain)
__device__ float g_pl[Bn * Hn * PART_N * Tn];          // per-partial running denom
__device__ float g_pacc[Bn * Hn * PART_N * Tn * Dn];   // per-partial weighted V acc
__device__ float g_o[BT * HIDn];                       // attention out, [b*T+t, h*D+d]
__device__ float g_opart[KSPLIT * BT * HIDn];          // split-K partials for Wo gemm

// ---------------- f32x2 packed-FMA helpers (Blackwell FFMA2) ----------------
#define FMA2(d, a, b, c) \
    asm("fma.rn.f32x2 %0, %1, %2, %3;" : "=l"(d) : "l"(a), "l"(b), "l"(c))
#define PACK2BC(d, x) \
    asm("mov.b64 %0, {%1, %1};" : "=l"(d) : "r"(__float_as_uint(x)))
#define UNPACK2(lo, hi, p) \
    asm("mov.b64 {%0, %1}, %2;" : "=f"(lo), "=f"(hi) : "l"(p))

// streaming-cache float4 load/store
__device__ __forceinline__ float4 ldcs4(const float* p) {
    return __ldcs((const float4*)p);
}
__device__ __forceinline__ void stcs4(float* p, float4 v) {
    __stcs((float4*)p, v);
}

// ---------------- GEMM: Y[m,n] = sum_k X[m,k] * W[n,k] ----------------
// M=32, K=4096, N=4096. Block 256 threads computes [32m x 128n] over a
// KCHUNK k-range. Smem-tiled, coalesced global loads, XOR-swizzled W tile
// (conflict-free transpose STS + compute LDS.128), f32x2 packed FMA inner loop.
__global__ void __launch_bounds__(256) gemm32(
        const float* __restrict__ X,   // nullptr -> use g_o
        const float* __restrict__ W0,
        const float* __restrict__ W1,
        const float* __restrict__ W2) {
    __shared__ __align__(16) float Xs[32][36];   // [k][m], stride 36 -> 16B-aligned rows, conflict-free STS
    __shared__ float Ws[32][132];                // [k][swizzled n], stride 132 -> conflict-free

    const float* Xp = X ? X : g_o;
    float* part = X ? g_qkv_part : g_opart;
    int mat = blockIdx.z;
    const float* W = (mat == 0) ? W0 : (mat == 1 ? W1 : W2);

    int tid = threadIdx.x;
    int lk = tid & 7;        // float4 index along k for loads (0..7)
    int lm = tid >> 3;       // row index for loads (0..31)
    int ng = tid & 31;       // n-group in compute (0..31) -> cols ng*4..+3
    int mg = tid >> 5;       // m-group / warp id (0..7)  -> rows mg*4..+3

    int n0blk = blockIdx.x * 128;
    int k0 = blockIdx.y * KCHUNK;

    unsigned long long acc[2][4];   // [m-pair][n], each is f32x2 (m0,m1)
#pragma unroll
    for (int i = 0; i < 2; i++)
#pragma unroll
        for (int j = 0; j < 4; j++) acc[i][j] = 0ull;

    const float* xg = Xp + (size_t)lm * HIDn + k0 + lk * 4;
    const float* wg = W + (size_t)(n0blk + lm) * HIDn + k0 + lk * 4;

    for (int kt = 0; kt < KCHUNK; kt += 32) {
        // --- load X tile [32m x 32k], store transposed ---
        float4 xv = *(const float4*)(xg + kt);
        Xs[lk * 4 + 0][lm] = xv.x;
        Xs[lk * 4 + 1][lm] = xv.y;
        Xs[lk * 4 + 2][lm] = xv.z;
        Xs[lk * 4 + 3][lm] = xv.w;
        // --- load W tile [128n x 32k], store transposed + XOR swizzle ---
#pragma unroll
        for (int it = 0; it < 4; it++) {
            int n = lm + it * 32;
            float4 wv = *(const float4*)(wg + (size_t)(it * 32) * HIDn + kt);
            int c = (((n >> 2) ^ lk) << 2) + (n & 3);
            Ws[lk * 4 + 0][c] = wv.x;
            Ws[lk * 4 + 1][c] = wv.y;
            Ws[lk * 4 + 2][c] = wv.z;
            Ws[lk * 4 + 3][c] = wv.w;
        }
        __syncthreads();

#pragma unroll
        for (int kk = 0; kk < 32; kk++) {
            int k4 = kk >> 2;
            // x pairs via one 128-bit shared load (broadcast across warp)
            ulonglong2 xp = *(const ulonglong2*)&Xs[kk][mg * 4];
            // w: de-swizzled LDS.128 (ng^k4 is a lane permutation -> conflict-free)
            float4 wv = *(const float4*)&Ws[kk][((ng ^ k4) << 2)];
            unsigned long long wb0, wb1, wb2, wb3;
            PACK2BC(wb0, wv.x); PACK2BC(wb1, wv.y);
            PACK2BC(wb2, wv.z); PACK2BC(wb3, wv.w);
            FMA2(acc[0][0], xp.x, wb0, acc[0][0]);
            FMA2(acc[0][1], xp.x, wb1, acc[0][1]);
            FMA2(acc[0][2], xp.x, wb2, acc[0][2]);
            FMA2(acc[0][3], xp.x, wb3, acc[0][3]);
            FMA2(acc[1][0], xp.y, wb0, acc[1][0]);
            FMA2(acc[1][1], xp.y, wb1, acc[1][1]);
            FMA2(acc[1][2], xp.y, wb2, acc[1][2]);
            FMA2(acc[1][3], xp.y, wb3, acc[1][3]);
        }
        __syncthreads();
    }

    // epilogue: thread owns rows mg*4..mg*4+3, cols n0blk + ng*4..+3
    float* pp = part + ((size_t)(mat * KSPLIT + blockIdx.y) * BT) * HIDn + n0blk + ng * 4;
#pragma unroll
    for (int mp = 0; mp < 2; mp++) {
        float lo[4], hi[4];
#pragma unroll
        for (int j = 0; j < 4; j++) UNPACK2(lo[j], hi[j], acc[mp][j]);
        *(float4*)(pp + (size_t)(mg * 4 + 2 * mp) * HIDn) =
            make_float4(lo[0], lo[1], lo[2], lo[3]);
        *(float4*)(pp + (size_t)(mg * 4 + 2 * mp + 1) * HIDn) =
            make_float4(hi[0], hi[1], hi[2], hi[3]);
    }
}

// ---------------- RoPE + scatter new k/v into d_out, q into scratch ----------------
__global__ void rope_scatter(const float* __restrict__ cs, const float* __restrict__ sn,
                             float* __restrict__ out) {
    int idx = blockIdx.x * blockDim.x + threadIdx.x;  // < 131072
    int d = idx & 127;
    int h = (idx >> 7) & 31;
    int t = (idx >> 12) & 3;
    int b = idx >> 14;
    int row = b * Tn + t;
    int col = h * Dn + d;
    int col2 = h * Dn + ((d + 64) & 127);

    float q = 0.f, k = 0.f, v = 0.f, q2 = 0.f, k2 = 0.f;
#pragma unroll
    for (int kz = 0; kz < KSPLIT; kz++) {
        size_t r = (size_t)row * HIDn;
        q  += __ldcs(&g_qkv_part[(size_t)(kz)              * BT * HIDn + r + col]);
        q2 += __ldcs(&g_qkv_part[(size_t)(kz)              * BT * HIDn + r + col2]);
        k  += __ldcs(&g_qkv_part[(size_t)(KSPLIT + kz)     * BT * HIDn + r + col]);
        k2 += __ldcs(&g_qkv_part[(size_t)(KSPLIT + kz)     * BT * HIDn + r + col2]);
        v  += __ldcs(&g_qkv_part[(size_t)(2 * KSPLIT + kz) * BT * HIDn + r + col]);
    }
    float sgn = (d < 64) ? -1.f : 1.f;   // rotate_half: [-x[64:], x[:64]]
    float c = cs[row * Dn + d];
    float s = sn[row * Dn + d];
    float qr = q * c + sgn * q2 * s;
    float kr = k * c + sgn * k2 * s;

    g_q[((size_t)(b * Hn + h) * Tn + t) * Dn + d] = qr;
    size_t ko = OUT_K_OFF + ((size_t)(b * Hn + h) * SFn + SCn + t) * Dn + d;
    out[ko] = kr;                 // k_full new row
    out[ko + KFULL_ELEMS] = v;    // v_full new row (no RoPE on v)
}

// online-softmax update for one k/v row (scores in log2 domain)
__device__ __forceinline__ void online_row(const float4 kc, const float4 vc,
                                           const float4 qf[4],
                                           float m[4], float l[4], float4 acc[4]) {
    const float sc = 0.088388347648318447f * 1.4426950408889634f;  // 1/sqrt(128) * log2(e)
    float p[4];
#pragma unroll
    for (int t = 0; t < 4; t++)
        p[t] = qf[t].x * kc.x + qf[t].y * kc.y + qf[t].z * kc.z + qf[t].w * kc.w;
#pragma unroll
    for (int off = 16; off; off >>= 1) {
#pragma unroll
        for (int t = 0; t < 4; t++)
            p[t] += __shfl_xor_sync(0xffffffffu, p[t], off);
    }
#pragma unroll
    for (int t = 0; t < 4; t++) {
        float s = p[t] * sc;
        if (s > m[t]) {                       // lazy rescale: rare after warmup
            float f = exp2f(m[t] - s);
            m[t] = s;
            l[t] *= f;
            acc[t].x *= f; acc[t].y *= f; acc[t].z *= f; acc[t].w *= f;
        }
        float e = exp2f(s - m[t]);
        l[t] += e;
        acc[t].x += e * vc.x; acc[t].y += e * vc.y;
        acc[t].z += e * vc.z; acc[t].w += e * vc.w;
    }
}

// ---------------- fused cache copy + flash-decode partial attention ----------------
// grid (17, H, B), block 128 (4 warps). splits 0..15: 256 cache rows each
// (copied to k_full/v_full while accumulating); the 4 warps' online states are
// merged in-block -> ONE partial slot per block. split 16: the 4 new rows.
__global__ void attn_copy(const float* __restrict__ ck, const float* __restrict__ cv,
                          float* out) {
    __shared__ float s_m[4][4];            // [warp][t]
    __shared__ float s_l[4][4];
    __shared__ float4 s_acc[3][4][32];     // warps 1..3: [warp-1][t][lane]

    int split = blockIdx.x;
    int h = blockIdx.y, b = blockIdx.z;
    int bh = b * Hn + h;
    int wid = threadIdx.x >> 5, lane = threadIdx.x & 31;

    float4 qf[4];
#pragma unroll
    for (int t = 0; t < 4; t++)
        qf[t] = *(const float4*)&g_q[((size_t)bh * Tn + t) * Dn + lane * 4];

    float m[4], l[4];
    float4 acc[4];
#pragma unroll
    for (int t = 0; t < 4; t++) { m[t] = -1e30f; l[t] = 0.f; acc[t] = make_float4(0, 0, 0, 0); }

    if (split < NSPLIT) {
        int s0 = split * 256 + wid * 64;
        const float* kp = ck + ((size_t)bh * SCn + s0) * Dn + lane * 4;
        const float* vp = cv + ((size_t)bh * SCn + s0) * Dn + lane * 4;
        float* kop = out + OUT_K_OFF + ((size_t)bh * SFn + s0) * Dn + lane * 4;
        float* vop = kop + KFULL_ELEMS;

        float4 kc = ldcs4(kp);
        float4 vc = ldcs4(vp);
        for (int r = 0; r < 64; r++) {
            float4 kn = kc, vn = vc;
            if (r < 63) {   // prefetch next row while processing current
                kn = ldcs4(kp + (size_t)(r + 1) * Dn);
                vn = ldcs4(vp + (size_t)(r + 1) * Dn);
            }
            stcs4(kop + (size_t)r * Dn, kc);   // fused cache->k_full copy
            stcs4(vop + (size_t)r * Dn, vc);
            online_row(kc, vc, qf, m, l, acc);
            kc = kn; vc = vn;
        }
    } else {
        // new rows already written to d_out by rope_scatter; read back, no copy
        const float* kr = out + OUT_K_OFF + ((size_t)bh * SFn + SCn + wid) * Dn + lane * 4;
        float4 kc = *(const float4*)kr;
        float4 vc = *(const float4*)(kr + KFULL_ELEMS);
        online_row(kc, vc, qf, m, l, acc);
    }

    // ---- in-block merge of the 4 warps' online-softmax states ----
    if (lane == 0) {
#pragma unroll
        for (int t = 0; t < 4; t++) { s_m[wid][t] = m[t]; s_l[wid][t] = l[t]; }
    }
    if (wid > 0) {
#pragma unroll
        for (int t = 0; t < 4; t++) s_acc[wid - 1][t][lane] = acc[t];
    }
    __syncthreads();

    if (wid == 0) {
        size_t base = ((size_t)bh * PART_N + split) * Tn;
#pragma unroll
        for (int t = 0; t < 4; t++) {
            float m0 = s_m[0][t], m1 = s_m[1][t], m2 = s_m[2][t], m3 = s_m[3][t];
            float M = fmaxf(fmaxf(m0, m1), fmaxf(m2, m3));
            float f0 = exp2f(m0 - M), f1 = exp2f(m1 - M);
            float f2 = exp2f(m2 - M), f3 = exp2f(m3 - M);
            float L = f0 * s_l[0][t] + f1 * s_l[1][t] + f2 * s_l[2][t] + f3 * s_l[3][t];
            float4 a1 = s_acc[0][t][lane], a2 = s_acc[1][t][lane], a3 = s_acc[2][t][lane];
            float4 A;
            A.x = f0 * acc[t].x + f1 * a1.x + f2 * a2.x + f3 * a3.x;
            A.y = f0 * acc[t].y + f1 * a1.y + f2 * a2.y + f3 * a3.y;
            A.z = f0 * acc[t].z + f1 * a1.z + f2 * a2.z + f3 * a3.z;
            A.w = f0 * acc[t].w + f1 * a1.w + f2 * a2.w + f3 * a3.w;
            if (lane == 0) { g_pm[base + t] = M; g_pl[base + t] = L; }
            *(float4*)&g_pacc[(base + t) * Dn + lane * 4] = A;
        }
    }
}

// ---------------- combine split partials -> attention output ----------------
// grid 256 (one block per bh), block 128: warp w handles t=w, lanes over d.
__global__ void combine_splits() {
    int bh = blockIdx.x;
    int b = bh >> 5, h = bh & 31;
    int t = threadIdx.x >> 5, lane = threadIdx.x & 31;
    size_t base = (size_t)bh * PART_N * Tn;

    // per-t softmax-merge scalars (broadcast loads within warp)
    float mx = -1e30f;
#pragma unroll
    for (int p = 0; p < PART_N; p++)
        mx = fmaxf(mx, g_pm[base + (size_t)p * Tn + t]);
    float den = 0.f;
    float e[PART_N];
#pragma unroll
    for (int p = 0; p < PART_N; p++) {
        e[p] = exp2f(g_pm[base + (size_t)p * Tn + t] - mx);
        den += g_pl[base + (size_t)p * Tn + t] * e[p];
    }

    float4 num = make_float4(0, 0, 0, 0);
#pragma unroll
    for (int p = 0; p < PART_N; p++) {
        float4 a = *(const float4*)&g_pacc[(base + (size_t)p * Tn + t) * Dn + lane * 4];
        num.x += e[p] * a.x; num.y += e[p] * a.y;
        num.z += e[p] * a.z; num.w += e[p] * a.w;
    }
    float inv = 1.f / den;
    float4 o = make_float4(num.x * inv, num.y * inv, num.z * inv, num.w * inv);
    *(float4*)&g_o[(size_t)(b * Tn + t) * HIDn + h * Dn + lane * 4] = o;
}

// ---------------- sum Wo split-K partials into final out ----------------
__global__ void finalize(float* __restrict__ out) {
    int idx = blockIdx.x * blockDim.x + threadIdx.x;  // < 131072
    float s = 0.f;
#pragma unroll
    for (int kz = 0; kz < KSPLIT; kz++)
        s += __ldcs(&g_opart[(size_t)kz * BT * HIDn + idx]);
    out[idx] = s;
}

extern "C" void kernel_launch(void* const* d_in, const int* in_sizes, int n_in,
                              void* d_out, int out_size) {
    const float* hidden  = (const float*)d_in[0];
    const float* cache_k = (const float*)d_in[1];
    const float* cache_v = (const float*)d_in[2];
    const float* cosp    = (const float*)d_in[3];
    const float* sinp    = (const float*)d_in[4];
    const float* Wq      = (const float*)d_in[5];
    const float* Wk      = (const float*)d_in[6];
    const float* Wv      = (const float*)d_in[7];
    const float* Wo      = (const float*)d_in[8];
    float* out = (float*)d_out;

    // 1) QKV projections (split-K partials)
    gemm32<<<dim3(32, KSPLIT, 3), 256>>>(hidden, Wq, Wk, Wv);
    // 2) reduce split-K + RoPE + scatter new k/v rows into d_out, q into scratch
    rope_scatter<<<512, 256>>>(cosp, sinp, out);
    // 3) fused cache copy + flash-decode partials (warps merged in-block)
    attn_copy<<<dim3(NSPLIT + 1, Hn, Bn), 128>>>(cache_k, cache_v, out);
    // 4) combine partials
    combine_splits<<<Bn * Hn, 128>>>();
    // 5) output projection (split-K partials, X = g_o selected by nullptr)
    gemm32<<<dim3(32, KSPLIT, 1), 256>>>(nullptr, Wo, Wo, Wo);
    // 6) reduce into d_out
    finalize<<<512, 256>>>(out);
}

// round 16
// speedup vs baseline: 1.1004x; 1.0487x over previous
#include <cuda_runtime.h>
#include <cuda_bf16.h>

// Problem constants
#define Bn   8
#define Tn   4
#define HIDn 4096
#define Hn   32
#define Dn   128
#define SCn  4096          // cache length
#define SFn  4100          // cache + T
#define BT   32            // B*T
#define KSPLIT 8
#define KCHUNK (HIDn / KSPLIT)   // 512
#define NSPLIT 16          // cache splits (256 rows each)
#define PART_N 17          // 16 cache splits + 1 new-token slot (warps merged in-block)
#define STAGES 6           // cp.async pipeline depth (rows in flight per warp)

#define OUT_K_OFF   ((size_t)131072)                       // out elems
#define KFULL_ELEMS ((size_t)Bn * Hn * SFn * Dn)           // 134,348,800

// ---------------- scratch (no allocations allowed) ----------------
__device__ float g_qkv_part[3 * KSPLIT * BT * HIDn];   // split-K partials for q,k,v proj
__device__ float g_q[Bn * Hn * Tn * Dn];               // RoPE'd q, [b,h,t,d]
__device__ float g_pm[Bn * Hn * PART_N * Tn];          // per-partial running max (log2 domain)
__device__ float g_pl[Bn * Hn * PART_N * Tn];          // per-partial running denom
__device__ float g_pacc[Bn * Hn * PART_N * Tn * Dn];   // per-partial weighted V acc
__device__ float g_o[BT * HIDn];                       // attention out, [b*T+t, h*D+d]
__device__ float g_opart[KSPLIT * BT * HIDn];          // split-K partials for Wo gemm

// ---------------- f32x2 packed-FMA helpers (Blackwell FFMA2) ----------------
#define FMA2(d, a, b, c) \
    asm("fma.rn.f32x2 %0, %1, %2, %3;" : "=l"(d) : "l"(a), "l"(b), "l"(c))
#define PACK2BC(d, x) \
    asm("mov.b64 %0, {%1, %1};" : "=l"(d) : "r"(__float_as_uint(x)))
#define UNPACK2(lo, hi, p) \
    asm("mov.b64 {%0, %1}, %2;" : "=f"(lo), "=f"(hi) : "l"(p))

// cp.async (LDGSTS) helpers: 16B per lane, L2-only (.cg)
#define CPA16(dst_smem, src_gmem) \
    asm volatile("cp.async.cg.shared.global [%0], [%1], 16;" \
                 :: "r"(dst_smem), "l"(src_gmem))
#define CPA_COMMIT() asm volatile("cp.async.commit_group;")
#define CPA_WAIT(n)  asm volatile("cp.async.wait_group %0;" :: "n"(n))

// streaming-cache float4 load/store
__device__ __forceinline__ float4 ldcs4(const float* p) {
    return __ldcs((const float4*)p);
}
__device__ __forceinline__ void stcs4(float* p, float4 v) {
    __stcs((float4*)p, v);
}

// ---------------- GEMM: Y[m,n] = sum_k X[m,k] * W[n,k] ----------------
// M=32, K=4096, N=4096. Block 256 threads computes [32m x 128n] over a
// KCHUNK k-range. Smem-tiled, coalesced global loads, XOR-swizzled W tile
// (conflict-free transpose STS + compute LDS.128), f32x2 packed FMA inner loop.
__global__ void __launch_bounds__(256) gemm32(
        const float* __restrict__ X,   // nullptr -> use g_o
        const float* __restrict__ W0,
        const float* __restrict__ W1,
        const float* __restrict__ W2) {
    __shared__ __align__(16) float Xs[32][36];   // [k][m], stride 36 -> 16B-aligned rows, conflict-free STS
    __shared__ float Ws[32][132];                // [k][swizzled n], stride 132 -> conflict-free

    const float* Xp = X ? X : g_o;
    float* part = X ? g_qkv_part : g_opart;
    int mat = blockIdx.z;
    const float* W = (mat == 0) ? W0 : (mat == 1 ? W1 : W2);

    int tid = threadIdx.x;
    int lk = tid & 7;        // float4 index along k for loads (0..7)
    int lm = tid >> 3;       // row index for loads (0..31)
    int ng = tid & 31;       // n-group in compute (0..31) -> cols ng*4..+3
    int mg = tid >> 5;       // m-group / warp id (0..7)  -> rows mg*4..+3

    int n0blk = blockIdx.x * 128;
    int k0 = blockIdx.y * KCHUNK;

    unsigned long long acc[2][4];   // [m-pair][n], each is f32x2 (m0,m1)
#pragma unroll
    for (int i = 0; i < 2; i++)
#pragma unroll
        for (int j = 0; j < 4; j++) acc[i][j] = 0ull;

    const float* xg = Xp + (size_t)lm * HIDn + k0 + lk * 4;
    const float* wg = W + (size_t)(n0blk + lm) * HIDn + k0 + lk * 4;

    for (int kt = 0; kt < KCHUNK; kt += 32) {
        // --- load X tile [32m x 32k], store transposed ---
        float4 xv = *(const float4*)(xg + kt);
        Xs[lk * 4 + 0][lm] = xv.x;
        Xs[lk * 4 + 1][lm] = xv.y;
        Xs[lk * 4 + 2][lm] = xv.z;
        Xs[lk * 4 + 3][lm] = xv.w;
        // --- load W tile [128n x 32k], store transposed + XOR swizzle ---
#pragma unroll
        for (int it = 0; it < 4; it++) {
            int n = lm + it * 32;
            float4 wv = *(const float4*)(wg + (size_t)(it * 32) * HIDn + kt);
            int c = (((n >> 2) ^ lk) << 2) + (n & 3);
            Ws[lk * 4 + 0][c] = wv.x;
            Ws[lk * 4 + 1][c] = wv.y;
            Ws[lk * 4 + 2][c] = wv.z;
            Ws[lk * 4 + 3][c] = wv.w;
        }
        __syncthreads();

#pragma unroll
        for (int kk = 0; kk < 32; kk++) {
            int k4 = kk >> 2;
            // x pairs via one 128-bit shared load (broadcast across warp)
            ulonglong2 xp = *(const ulonglong2*)&Xs[kk][mg * 4];
            // w: de-swizzled LDS.128 (ng^k4 is a lane permutation -> conflict-free)
            float4 wv = *(const float4*)&Ws[kk][((ng ^ k4) << 2)];
            unsigned long long wb0, wb1, wb2, wb3;
            PACK2BC(wb0, wv.x); PACK2BC(wb1, wv.y);
            PACK2BC(wb2, wv.z); PACK2BC(wb3, wv.w);
            FMA2(acc[0][0], xp.x, wb0, acc[0][0]);
            FMA2(acc[0][1], xp.x, wb1, acc[0][1]);
            FMA2(acc[0][2], xp.x, wb2, acc[0][2]);
            FMA2(acc[0][3], xp.x, wb3, acc[0][3]);
            FMA2(acc[1][0], xp.y, wb0, acc[1][0]);
            FMA2(acc[1][1], xp.y, wb1, acc[1][1]);
            FMA2(acc[1][2], xp.y, wb2, acc[1][2]);
            FMA2(acc[1][3], xp.y, wb3, acc[1][3]);
        }
        __syncthreads();
    }

    // epilogue: thread owns rows mg*4..mg*4+3, cols n0blk + ng*4..+3
    float* pp = part + ((size_t)(mat * KSPLIT + blockIdx.y) * BT) * HIDn + n0blk + ng * 4;
#pragma unroll
    for (int mp = 0; mp < 2; mp++) {
        float lo[4], hi[4];
#pragma unroll
        for (int j = 0; j < 4; j++) UNPACK2(lo[j], hi[j], acc[mp][j]);
        *(float4*)(pp + (size_t)(mg * 4 + 2 * mp) * HIDn) =
            make_float4(lo[0], lo[1], lo[2], lo[3]);
        *(float4*)(pp + (size_t)(mg * 4 + 2 * mp + 1) * HIDn) =
            make_float4(hi[0], hi[1], hi[2], hi[3]);
    }
}

// ---------------- RoPE + scatter new k/v into d_out, q into scratch ----------------
__global__ void rope_scatter(const float* __restrict__ cs, const float* __restrict__ sn,
                             float* __restrict__ out) {
    int idx = blockIdx.x * blockDim.x + threadIdx.x;  // < 131072
    int d = idx & 127;
    int h = (idx >> 7) & 31;
    int t = (idx >> 12) & 3;
    int b = idx >> 14;
    int row = b * Tn + t;
    int col = h * Dn + d;
    int col2 = h * Dn + ((d + 64) & 127);

    float q = 0.f, k = 0.f, v = 0.f, q2 = 0.f, k2 = 0.f;
#pragma unroll
    for (int kz = 0; kz < KSPLIT; kz++) {
        size_t r = (size_t)row * HIDn;
        q  += __ldcs(&g_qkv_part[(size_t)(kz)              * BT * HIDn + r + col]);
        q2 += __ldcs(&g_qkv_part[(size_t)(kz)              * BT * HIDn + r + col2]);
        k  += __ldcs(&g_qkv_part[(size_t)(KSPLIT + kz)     * BT * HIDn + r + col]);
        k2 += __ldcs(&g_qkv_part[(size_t)(KSPLIT + kz)     * BT * HIDn + r + col2]);
        v  += __ldcs(&g_qkv_part[(size_t)(2 * KSPLIT + kz) * BT * HIDn + r + col]);
    }
    float sgn = (d < 64) ? -1.f : 1.f;   // rotate_half: [-x[64:], x[:64]]
    float c = cs[row * Dn + d];
    float s = sn[row * Dn + d];
    float qr = q * c + sgn * q2 * s;
    float kr = k * c + sgn * k2 * s;

    g_q[((size_t)(b * Hn + h) * Tn + t) * Dn + d] = qr;
    size_t ko = OUT_K_OFF + ((size_t)(b * Hn + h) * SFn + SCn + t) * Dn + d;
    out[ko] = kr;                 // k_full new row
    out[ko + KFULL_ELEMS] = v;    // v_full new row (no RoPE on v)
}

// online-softmax update for one k/v row (scores in log2 domain)
__device__ __forceinline__ void online_row(const float4 kc, const float4 vc,
                                           const float4 qf[4],
                                           float m[4], float l[4], float4 acc[4]) {
    const float sc = 0.088388347648318447f * 1.4426950408889634f;  // 1/sqrt(128) * log2(e)
    float p[4];
#pragma unroll
    for (int t = 0; t < 4; t++)
        p[t] = qf[t].x * kc.x + qf[t].y * kc.y + qf[t].z * kc.z + qf[t].w * kc.w;
#pragma unroll
    for (int off = 16; off; off >>= 1) {
#pragma unroll
        for (int t = 0; t < 4; t++)
            p[t] += __shfl_xor_sync(0xffffffffu, p[t], off);
    }
#pragma unroll
    for (int t = 0; t < 4; t++) {
        float s = p[t] * sc;
        if (s > m[t]) {                       // lazy rescale: rare after warmup
            float f = exp2f(m[t] - s);
            m[t] = s;
            l[t] *= f;
            acc[t].x *= f; acc[t].y *= f; acc[t].z *= f; acc[t].w *= f;
        }
        float e = exp2f(s - m[t]);
        l[t] += e;
        acc[t].x += e * vc.x; acc[t].y += e * vc.y;
        acc[t].z += e * vc.z; acc[t].w += e * vc.w;
    }
}

// ---------------- fused cache copy + flash-decode partial attention ----------------
// grid (17, H, B), block 128 (4 warps). splits 0..15: 256 cache rows each,
// streamed through a per-warp cp.async smem ring (12 loads in flight/warp),
// copied to k_full/v_full while accumulating online softmax; the 4 warps'
// states are merged in-block -> ONE partial slot. split 16: the 4 new rows.
__global__ void __launch_bounds__(128) attn_copy(
        const float* __restrict__ ck, const float* __restrict__ cv, float* out) {
    __shared__ __align__(16) float s_k[4][STAGES][Dn];   // 12 KB
    __shared__ __align__(16) float s_v[4][STAGES][Dn];   // 12 KB
    __shared__ float s_m[4][4];            // [warp][t]
    __shared__ float s_l[4][4];
    __shared__ float4 s_acc[3][4][32];     // warps 1..3: [warp-1][t][lane]

    int split = blockIdx.x;
    int h = blockIdx.y, b = blockIdx.z;
    int bh = b * Hn + h;
    int wid = threadIdx.x >> 5, lane = threadIdx.x & 31;

    float4 qf[4];
#pragma unroll
    for (int t = 0; t < 4; t++)
        qf[t] = *(const float4*)&g_q[((size_t)bh * Tn + t) * Dn + lane * 4];

    float m[4], l[4];
    float4 acc[4];
#pragma unroll
    for (int t = 0; t < 4; t++) { m[t] = -1e30f; l[t] = 0.f; acc[t] = make_float4(0, 0, 0, 0); }

    if (split < NSPLIT) {
        int s0 = split * 256 + wid * 64;
        const float* kp = ck + ((size_t)bh * SCn + s0) * Dn + lane * 4;
        const float* vp = cv + ((size_t)bh * SCn + s0) * Dn + lane * 4;
        float* kop = out + OUT_K_OFF + ((size_t)bh * SFn + s0) * Dn + lane * 4;
        float* vop = kop + KFULL_ELEMS;

        // lane-private 16B slots in the smem ring
        unsigned sk = (unsigned)__cvta_generic_to_shared(&s_k[wid][0][lane * 4]);
        unsigned sv = (unsigned)__cvta_generic_to_shared(&s_v[wid][0][lane * 4]);
        const unsigned stB = Dn * 4;   // 512 B per stage

        // prologue: fill the ring (one commit group per row)
#pragma unroll
        for (int i = 0; i < STAGES; i++) {
            CPA16(sk + i * stB, kp + (size_t)i * Dn);
            CPA16(sv + i * stB, vp + (size_t)i * Dn);
            CPA_COMMIT();
        }

        int st = 0;
        for (int r = 0; r < 64; r++) {
            CPA_WAIT(STAGES - 1);        // row r's group has landed
            float4 kc = *(const float4*)&s_k[wid][st][lane * 4];
            float4 vc = *(const float4*)&s_v[wid][st][lane * 4];
            stcs4(kop + (size_t)r * Dn, kc);   // fused cache->k_full copy
            stcs4(vop + (size_t)r * Dn, vc);
            online_row(kc, vc, qf, m, l, acc);
            int nr = r + STAGES;
            if (nr < 64) {               // refill this stage (lane-private slot)
                CPA16(sk + st * stB, kp + (size_t)nr * Dn);
                CPA16(sv + st * stB, vp + (size_t)nr * Dn);
            }
            CPA_COMMIT();                // keep group accounting uniform
            st = (st + 1 == STAGES) ? 0 : st + 1;
        }
    } else {
        // new rows already written to d_out by rope_scatter; read back, no copy
        const float* kr = out + OUT_K_OFF + ((size_t)bh * SFn + SCn + wid) * Dn + lane * 4;
        float4 kc = *(const float4*)kr;
        float4 vc = *(const float4*)(kr + KFULL_ELEMS);
        online_row(kc, vc, qf, m, l, acc);
    }

    // ---- in-block merge of the 4 warps' online-softmax states ----
    if (lane == 0) {
#pragma unroll
        for (int t = 0; t < 4; t++) { s_m[wid][t] = m[t]; s_l[wid][t] = l[t]; }
    }
    if (wid > 0) {
#pragma unroll
        for (int t = 0; t < 4; t++) s_acc[wid - 1][t][lane] = acc[t];
    }
    __syncthreads();

    if (wid == 0) {
        size_t base = ((size_t)bh * PART_N + split) * Tn;
#pragma unroll
        for (int t = 0; t < 4; t++) {
            float m0 = s_m[0][t], m1 = s_m[1][t], m2 = s_m[2][t], m3 = s_m[3][t];
            float M = fmaxf(fmaxf(m0, m1), fmaxf(m2, m3));
            float f0 = exp2f(m0 - M), f1 = exp2f(m1 - M);
            float f2 = exp2f(m2 - M), f3 = exp2f(m3 - M);
            float L = f0 * s_l[0][t] + f1 * s_l[1][t] + f2 * s_l[2][t] + f3 * s_l[3][t];
            float4 a1 = s_acc[0][t][lane], a2 = s_acc[1][t][lane], a3 = s_acc[2][t][lane];
            float4 A;
            A.x = f0 * acc[t].x + f1 * a1.x + f2 * a2.x + f3 * a3.x;
            A.y = f0 * acc[t].y + f1 * a1.y + f2 * a2.y + f3 * a3.y;
            A.z = f0 * acc[t].z + f1 * a1.z + f2 * a2.z + f3 * a3.z;
            A.w = f0 * acc[t].w + f1 * a1.w + f2 * a2.w + f3 * a3.w;
            if (lane == 0) { g_pm[base + t] = M; g_pl[base + t] = L; }
            *(float4*)&g_pacc[(base + t) * Dn + lane * 4] = A;
        }
    }
}

// ---------------- combine split partials -> attention output ----------------
// grid 256 (one block per bh), block 128: warp w handles t=w, lanes over d.
__global__ void combine_splits() {
    int bh = blockIdx.x;
    int b = bh >> 5, h = bh & 31;
    int t = threadIdx.x >> 5, lane = threadIdx.x & 31;
    size_t base = (size_t)bh * PART_N * Tn;

    // per-t softmax-merge scalars (broadcast loads within warp)
    float mx = -1e30f;
#pragma unroll
    for (int p = 0; p < PART_N; p++)
        mx = fmaxf(mx, g_pm[base + (size_t)p * Tn + t]);
    float den = 0.f;
    float e[PART_N];
#pragma unroll
    for (int p = 0; p < PART_N; p++) {
        e[p] = exp2f(g_pm[base + (size_t)p * Tn + t] - mx);
        den += g_pl[base + (size_t)p * Tn + t] * e[p];
    }

    float4 num = make_float4(0, 0, 0, 0);
#pragma unroll
    for (int p = 0; p < PART_N; p++) {
        float4 a = *(const float4*)&g_pacc[(base + (size_t)p * Tn + t) * Dn + lane * 4];
        num.x += e[p] * a.x; num.y += e[p] * a.y;
        num.z += e[p] * a.z; num.w += e[p] * a.w;
    }
    float inv = 1.f / den;
    float4 o = make_float4(num.x * inv, num.y * inv, num.z * inv, num.w * inv);
    *(float4*)&g_o[(size_t)(b * Tn + t) * HIDn + h * Dn + lane * 4] = o;
}

// ---------------- sum Wo split-K partials into final out ----------------
__global__ void finalize(float* __restrict__ out) {
    int idx = blockIdx.x * blockDim.x + threadIdx.x;  // < 131072
    float s = 0.f;
#pragma unroll
    for (int kz = 0; kz < KSPLIT; kz++)
        s += __ldcs(&g_opart[(size_t)kz * BT * HIDn + idx]);
    out[idx] = s;
}

extern "C" void kernel_launch(void* const* d_in, const int* in_sizes, int n_in,
                              void* d_out, int out_size) {
    const float* hidden  = (const float*)d_in[0];
    const float* cache_k = (const float*)d_in[1];
    const float* cache_v = (const float*)d_in[2];
    const float* cosp    = (const float*)d_in[3];
    const float* sinp    = (const float*)d_in[4];
    const float* Wq      = (const float*)d_in[5];
    const float* Wk      = (const float*)d_in[6];
    const float* Wv      = (const float*)d_in[7];
    const float* Wo      = (const float*)d_in[8];
    float* out = (float*)d_out;

    // 1) QKV projections (split-K partials)
    gemm32<<<dim3(32, KSPLIT, 3), 256>>>(hidden, Wq, Wk, Wv);
    // 2) reduce split-K + RoPE + scatter new k/v rows into d_out, q into scratch
    rope_scatter<<<512, 256>>>(cosp, sinp, out);
    // 3) fused cache copy + flash-decode partials (cp.async pipelined)
    attn_copy<<<dim3(NSPLIT + 1, Hn, Bn), 128>>>(cache_k, cache_v, out);
    // 4) combine partials
    combine_splits<<<Bn * Hn, 128>>>();
    // 5) output projection (split-K partials, X = g_o selected by nullptr)
    gemm32<<<dim3(32, KSPLIT, 1), 256>>>(nullptr, Wo, Wo, Wo);
    // 6) reduce into d_out
    finalize<<<512, 256>>>(out);
}